// round 2
// baseline (speedup 1.0000x reference)
#include <cuda_runtime.h>
#include <cstdint>

#define N_ROWS 32768
#define DIM    256
#define NE     8192
#define TM     64
#define TN     64
#define NCHUNK (NE / TN)

#define INDOFF  (N_ROWS * DIM)         // 2097152
#define LOSSOFF (INDOFF + N_ROWS)      // 2129920

// Scratch (device globals: allocation-free per harness rules)
__device__ float g_embedT[(size_t)NE * DIM];  // [8192][256] transposed codebook
__device__ float g_norms[NE];                 // ||e_j||^2
__device__ float g_partial[N_ROWS / TM];      // per-block loss partials (512)

// ---------------------------------------------------------------------------
// Prep 1: transpose embed [256][8192] -> embedT [8192][256]
// ---------------------------------------------------------------------------
__global__ void vq_transpose(const float* __restrict__ embed) {
    __shared__ float tile[32][33];
    int jB = blockIdx.x * 32;   // code dim
    int dB = blockIdx.y * 32;   // feature dim
    int tx = threadIdx.x, ty = threadIdx.y;   // (32, 8)
    #pragma unroll
    for (int r = ty; r < 32; r += 8)
        tile[r][tx] = embed[(size_t)(dB + r) * NE + jB + tx];
    __syncthreads();
    #pragma unroll
    for (int r = ty; r < 32; r += 8)
        g_embedT[(size_t)(jB + r) * DIM + dB + tx] = tile[tx][r];
}

// ---------------------------------------------------------------------------
// Prep 2: norms[j] = sum_d embedT[j][d]^2  (one warp per code, coalesced)
// ---------------------------------------------------------------------------
__global__ void vq_norms() {
    int warp = threadIdx.x >> 5, lane = threadIdx.x & 31;
    int j = blockIdx.x * 8 + warp;
    const float4* row = (const float4*)(g_embedT + (size_t)j * DIM);
    float s = 0.f;
    #pragma unroll
    for (int i = lane; i < DIM / 4; i += 32) {
        float4 v = row[i];
        s += v.x * v.x + v.y * v.y + v.z * v.z + v.w * v.w;
    }
    #pragma unroll
    for (int o = 16; o; o >>= 1) s += __shfl_xor_sync(0xFFFFFFFFu, s, o);
    if (lane == 0) g_norms[j] = s;
}

// ---------------------------------------------------------------------------
// Main: fused SGEMM (scores) + argmin + gather + straight-through + loss
// 256 threads, 64x64 tile, 4x4 microtile. A persistent in smem, B streamed.
// ---------------------------------------------------------------------------
__global__ void __launch_bounds__(256, 1)
vq_main(const float* __restrict__ input, const float* __restrict__ embed,
        float* __restrict__ out) {
    extern __shared__ float smem[];
    float* As = smem;                    // [256][64] : As[k*64 + m]
    float* Bs = smem + 256 * 64;         // [256][64] : Bs[k*64 + j]
    unsigned long long* bestP = (unsigned long long*)(smem + 2 * 256 * 64); // 64
    int*   sIdx = (int*)(bestP + 64);    // 64
    float* red  = (float*)(sIdx + 64);   // 256

    const int tid = threadIdx.x;
    const int tx  = tid & 15;            // 0..15 -> 4 cols each
    const int ty  = tid >> 4;            // 0..15 -> 4 rows each
    const int rowBase = blockIdx.x * TM;

    if (tid < TM) bestP[tid] = 0xFFFFFFFFFFFFFFFFull;

    // ---- stage A once: input rows rowBase..rowBase+63, stored transposed ----
    {
        const float4* Ain = (const float4*)(input + (size_t)rowBase * DIM);
        #pragma unroll
        for (int p = 0; p < 16; p++) {
            int f4 = p * 256 + tid;        // 0..4095 float4s (64 rows x 64 f4)
            int r  = f4 >> 6;              // row within tile
            int kb = (f4 & 63) << 2;       // k base
            float4 v = Ain[f4];
            As[(kb + 0) * TM + r] = v.x;
            As[(kb + 1) * TM + r] = v.y;
            As[(kb + 2) * TM + r] = v.z;
            As[(kb + 3) * TM + r] = v.w;
        }
    }

    unsigned int bKey[4];
    int bIdx[4];
    #pragma unroll
    for (int i = 0; i < 4; i++) { bKey[i] = 0xFFFFFFFFu; bIdx[i] = 0; }

    for (int c = 0; c < NCHUNK; c++) {
        const int cb = c * TN;
        __syncthreads();   // previous chunk's compute done before Bs overwrite
        {
            const float* Bsrc = embed + cb;   // embed[k][j] row-major stride NE
            #pragma unroll
            for (int p = 0; p < 16; p++) {
                int f4 = p * 256 + tid;       // 4096 float4s (256 k x 16 f4)
                int k  = f4 >> 4;
                int jb = (f4 & 15) << 2;
                *(float4*)(Bs + k * TN + jb) =
                    *(const float4*)(Bsrc + (size_t)k * NE + jb);
            }
        }
        __syncthreads();

        float acc[4][4] = {};
        #pragma unroll 8
        for (int k = 0; k < DIM; k++) {
            float4 av = *(const float4*)(As + k * TM + (ty << 2));
            float4 bv = *(const float4*)(Bs + k * TN + (tx << 2));
            float a_[4] = {av.x, av.y, av.z, av.w};
            float b_[4] = {bv.x, bv.y, bv.z, bv.w};
            #pragma unroll
            for (int i = 0; i < 4; i++)
                #pragma unroll
                for (int jj = 0; jj < 4; jj++)
                    acc[i][jj] = fmaf(a_[i], b_[jj], acc[i][jj]);
        }

        // epilogue: score = ||e||^2 - 2*dot ; argmin with first-index ties
        #pragma unroll
        for (int jj = 0; jj < 4; jj++) {
            int jg = cb + (tx << 2) + jj;
            float nrm = g_norms[jg];
            #pragma unroll
            for (int i = 0; i < 4; i++) {
                float s = fmaf(-2.f, acc[i][jj], nrm);
                unsigned u = __float_as_uint(s);
                unsigned key = (u & 0x80000000u) ? ~u : (u | 0x80000000u);
                if (key < bKey[i]) { bKey[i] = key; bIdx[i] = jg; }
            }
        }
    }

    // ---- combine argmin across threads (min key, then min index on ties) ----
    #pragma unroll
    for (int i = 0; i < 4; i++) {
        unsigned long long p =
            ((unsigned long long)bKey[i] << 32) | (unsigned)bIdx[i];
        atomicMin(&bestP[(ty << 2) + i], p);
    }
    __syncthreads();

    if (tid < TM) {
        int j = (int)(bestP[tid] & 0xFFFFFFFFull);
        sIdx[tid] = j;
        out[INDOFF + rowBase + tid] = (float)j;   // embed_ind as float
    }
    __syncthreads();

    // ---- gather + straight-through output + loss partial (d = tid) ----
    float lsum = 0.f;
    for (int r = 0; r < TM; r++) {
        int j = sIdx[r];
        float q = g_embedT[(size_t)j * DIM + tid];
        float x = input[(size_t)(rowBase + r) * DIM + tid];
        float d = q - x;                    // matches stop_grad(q) - x
        out[(size_t)(rowBase + r) * DIM + tid] = x + d; // straight-through
        lsum += d * d;
    }
    red[tid] = lsum;
    __syncthreads();
    #pragma unroll
    for (int s = 128; s; s >>= 1) {
        if (tid < s) red[tid] += red[tid + s];
        __syncthreads();
    }
    if (tid == 0) g_partial[blockIdx.x] = red[0];
}

// ---------------------------------------------------------------------------
// Final: deterministic loss reduction (512 partials, fixed order)
// ---------------------------------------------------------------------------
__global__ void vq_loss_final(float* __restrict__ out) {
    __shared__ float red[512];
    red[threadIdx.x] = g_partial[threadIdx.x];
    __syncthreads();
    #pragma unroll
    for (int s = 256; s; s >>= 1) {
        if (threadIdx.x < s) red[threadIdx.x] += red[threadIdx.x + s];
        __syncthreads();
    }
    if (threadIdx.x == 0)
        out[LOSSOFF] = red[0] * (1.0f / (float)(N_ROWS * DIM));
}

// ---------------------------------------------------------------------------
extern "C" void kernel_launch(void* const* d_in, const int* in_sizes, int n_in,
                              void* d_out, int out_size) {
    const float* input = (const float*)d_in[0];   // [8,64,64,256] -> [32768,256]
    const float* embed = (const float*)d_in[1];   // [256,8192]
    float* out = (float*)d_out;

    const int smemBytes = (2 * 256 * 64) * 4      // As + Bs
                        + 64 * 8 + 64 * 4 + 256 * 4;
    cudaFuncSetAttribute(vq_main, cudaFuncAttributeMaxDynamicSharedMemorySize,
                         smemBytes);

    vq_transpose<<<dim3(NE / 32, DIM / 32), dim3(32, 8)>>>(embed);
    vq_norms<<<NE / 8, 256>>>();
    vq_main<<<N_ROWS / TM, 256, smemBytes>>>(input, embed, out);
    vq_loss_final<<<1, 512>>>(out);
}